// round 1
// baseline (speedup 1.0000x reference)
#include <cuda_runtime.h>

#define B_   8
#define T_   512
#define H_   768
#define L_   12
#define FF_  3072
#define BT_  (B_*T_)
#define EPS_ 1e-5f

// ---------------- scratch (static device globals; no allocation) ----------
__device__ float g_h  [BT_*H_];
__device__ float g_xk [BT_*H_];
__device__ float g_xv [BT_*H_];
__device__ float g_xr [BT_*H_];
__device__ float g_k  [BT_*H_];
__device__ float g_v  [BT_*H_];
__device__ float g_r  [BT_*H_];
__device__ float g_att[BT_*H_];
__device__ float g_kf [BT_*FF_];

// ---------------- block reduction (blockDim == 256) ------------------------
__device__ __forceinline__ float bsum256(float val, float* red) {
    int lane = threadIdx.x & 31;
    int w    = threadIdx.x >> 5;
#pragma unroll
    for (int o = 16; o; o >>= 1) val += __shfl_xor_sync(0xffffffffu, val, o);
    __syncthreads();                 // protect red[] reuse across calls
    if (lane == 0) red[w] = val;
    __syncthreads();
    float s = 0.f;
#pragma unroll
    for (int i = 0; i < 8; i++) s += red[i];
    return s;
}

// ---------------- plain LayerNorm (one block per row) ----------------------
__global__ void ln_kernel(const float* __restrict__ in,
                          const float* __restrict__ w,
                          const float* __restrict__ b,
                          float* __restrict__ out) {
    __shared__ float red[8];
    size_t base = (size_t)blockIdx.x * H_;
    float c[3];
    float s = 0.f, s2 = 0.f;
#pragma unroll
    for (int i = 0; i < 3; i++) {
        int j = threadIdx.x + i * 256;
        c[i] = in[base + j];
        s += c[i]; s2 += c[i] * c[i];
    }
    s  = bsum256(s,  red);
    s2 = bsum256(s2, red);
    float m  = s / H_;
    float v  = s2 / H_ - m * m;
    float rs = rsqrtf(v + EPS_);
#pragma unroll
    for (int i = 0; i < 3; i++) {
        int j = threadIdx.x + i * 256;
        out[base + j] = (c[i] - m) * rs * w[j] + b[j];
    }
}

// ---------------- LN + token-shift + lerp-mix (one block per (b,t) row) ----
// Produces xk, xv (optional), xr mixed inputs from hidden state h.
__global__ void prep_mix(const float* __restrict__ h,
                         const float* __restrict__ lnw, const float* __restrict__ lnb,
                         const float* __restrict__ mk,  const float* __restrict__ mv,
                         const float* __restrict__ mr,
                         float* __restrict__ xk, float* __restrict__ xv,
                         float* __restrict__ xr) {
    __shared__ float red[8];
    int row = blockIdx.x;
    int t   = row % T_;
    const float* cur = h + (size_t)row * H_;
    float c[3], p[3];
    float sc = 0.f, sc2 = 0.f, sp = 0.f, sp2 = 0.f;
#pragma unroll
    for (int i = 0; i < 3; i++) {
        int j = threadIdx.x + i * 256;
        c[i] = cur[j];
        sc += c[i]; sc2 += c[i] * c[i];
        p[i] = (t > 0) ? cur[j - H_] : 0.f;
        sp += p[i]; sp2 += p[i] * p[i];
    }
    sc  = bsum256(sc,  red);
    sc2 = bsum256(sc2, red);
    sp  = bsum256(sp,  red);
    sp2 = bsum256(sp2, red);
    float mc = sc / H_, vc = sc2 / H_ - mc * mc, rc = rsqrtf(vc + EPS_);
    float mp = sp / H_, vp = sp2 / H_ - mp * mp, rp = rsqrtf(vp + EPS_);
#pragma unroll
    for (int i = 0; i < 3; i++) {
        int j = threadIdx.x + i * 256;
        float w = lnw[j], bb = lnb[j];
        float hn = (c[i] - mc) * rc * w + bb;
        float sh = (t > 0) ? ((p[i] - mp) * rp * w + bb) : 0.f;
        size_t idx = (size_t)row * H_ + j;
        float k_ = mk[j];
        xk[idx] = hn * k_ + sh * (1.f - k_);
        if (xv) {
            float v_ = mv[j];
            xv[idx] = hn * v_ + sh * (1.f - v_);
        }
        float r_ = mr[j];
        xr[idx] = hn * r_ + sh * (1.f - r_);
    }
}

// ---------------- WKV scan: one thread per (b, channel), fuses r-gate ------
__global__ void wkv_kernel(const float* __restrict__ k,
                           const float* __restrict__ v,
                           const float* __restrict__ r,
                           const float* __restrict__ td,
                           const float* __restrict__ tf,
                           float* __restrict__ att) {
    int c = blockIdx.x * blockDim.x + threadIdx.x;
    if (c >= B_ * H_) return;
    int b = c / H_, hh = c % H_;
    float w = -expf(td[hh]);
    float u = tf[hh];
    float num = 0.f, den = 0.f, mx = -1e38f;
    size_t base = (size_t)b * T_ * H_ + hh;
    for (int t = 0; t < T_; t++) {
        size_t idx = base + (size_t)t * H_;
        float kt = k[idx], vt = v[idx];
        float a  = kt + u;
        float mo = fmaxf(mx, a);
        float e1 = expf(mx - mo), e2 = expf(a - mo);
        float out = (e1 * num + e2 * vt) / (e1 * den + e2);
        att[idx] = out * r[idx];
        float ms = fmaxf(mx + w, kt);
        float f1 = expf(mx + w - ms), f2 = expf(kt - ms);
        num = f1 * num + f2 * vt;
        den = f1 * den + f2;
        mx  = ms;
    }
}

// ---------------- 128x128x8 fp32 tiled GEMM, templated epilogues -----------
// EPI: 0 C=acc, 1 C=sigmoid(acc), 2 C+=acc, 3 C+=aux*acc, 4 C=relu(acc)^2
#define GM 128
#define GN 128
#define GK 8

template <int EPI>
__global__ __launch_bounds__(256, 2)
void sgemm(const float* __restrict__ A, const float* __restrict__ B,
           float* __restrict__ C, const float* __restrict__ aux,
           int M, int N, int K) {
    __shared__ __align__(16) float As[GK][GM + 4];
    __shared__ __align__(16) float Bs[GK][GN];

    int tid = threadIdx.x;
    int bm  = blockIdx.y * GM;
    int bn  = blockIdx.x * GN;
    int tx  = tid & 15;       // 0..15 -> 8 cols each
    int ty  = tid >> 4;       // 0..15 -> 8 rows each

    int arow = tid >> 1;            // 0..127
    int acol = (tid & 1) * 4;       // 0 or 4
    int brow = tid >> 5;            // 0..7
    int bcol = (tid & 31) * 4;      // 0..124

    const float* Aptr = A + (size_t)(bm + arow) * K + acol;
    const float* Bptr = B + (size_t)brow * N + bn + bcol;

    float acc[8][8];
#pragma unroll
    for (int i = 0; i < 8; i++)
#pragma unroll
        for (int j = 0; j < 8; j++) acc[i][j] = 0.f;

    for (int k0 = 0; k0 < K; k0 += GK) {
        float4 av = *(const float4*)Aptr;
        float4 bv = *(const float4*)Bptr;
        As[acol + 0][arow] = av.x;
        As[acol + 1][arow] = av.y;
        As[acol + 2][arow] = av.z;
        As[acol + 3][arow] = av.w;
        *(float4*)&Bs[brow][bcol] = bv;
        __syncthreads();
#pragma unroll
        for (int kk = 0; kk < GK; kk++) {
            float4 a0 = *(const float4*)&As[kk][ty * 8];
            float4 a1 = *(const float4*)&As[kk][ty * 8 + 4];
            float4 b0 = *(const float4*)&Bs[kk][tx * 8];
            float4 b1 = *(const float4*)&Bs[kk][tx * 8 + 4];
            float a[8] = {a0.x, a0.y, a0.z, a0.w, a1.x, a1.y, a1.z, a1.w};
            float b[8] = {b0.x, b0.y, b0.z, b0.w, b1.x, b1.y, b1.z, b1.w};
#pragma unroll
            for (int i = 0; i < 8; i++)
#pragma unroll
                for (int j = 0; j < 8; j++)
                    acc[i][j] = fmaf(a[i], b[j], acc[i][j]);
        }
        __syncthreads();
        Aptr += GK;
        Bptr += (size_t)GK * N;
    }

#pragma unroll
    for (int i = 0; i < 8; i++) {
        size_t rbase = (size_t)(bm + ty * 8 + i) * N + bn + tx * 8;
#pragma unroll
        for (int j = 0; j < 8; j++) {
            size_t idx = rbase + j;
            float v = acc[i][j];
            if (EPI == 0)      C[idx] = v;
            else if (EPI == 1) C[idx] = 1.f / (1.f + expf(-v));
            else if (EPI == 2) C[idx] += v;
            else if (EPI == 3) C[idx] += aux[idx] * v;
            else {             float rr = fmaxf(v, 0.f); C[idx] = rr * rr; }
        }
    }
}

// ---------------- host orchestration ---------------------------------------
extern "C" void kernel_launch(void* const* d_in, const int* in_sizes, int n_in,
                              void* d_out, int out_size) {
    (void)in_sizes; (void)n_in; (void)out_size;
    const float* x     = (const float*)d_in[0];
    const float* prew  = (const float*)d_in[1];
    const float* preb  = (const float*)d_in[2];
    const float* ln1w  = (const float*)d_in[3];
    const float* ln1b  = (const float*)d_in[4];
    const float* ln2w  = (const float*)d_in[5];
    const float* ln2b  = (const float*)d_in[6];
    const float* td    = (const float*)d_in[7];
    const float* tf    = (const float*)d_in[8];
    const float* amk   = (const float*)d_in[9];
    const float* amv   = (const float*)d_in[10];
    const float* amr   = (const float*)d_in[11];
    const float* Wk    = (const float*)d_in[12];
    const float* Wv    = (const float*)d_in[13];
    const float* Wr    = (const float*)d_in[14];
    const float* Wo    = (const float*)d_in[15];
    const float* fmk   = (const float*)d_in[16];
    const float* fmr   = (const float*)d_in[17];
    const float* Fk    = (const float*)d_in[18];
    const float* Fv    = (const float*)d_in[19];
    const float* Fr    = (const float*)d_in[20];
    const float* lnow  = (const float*)d_in[21];
    const float* lnob  = (const float*)d_in[22];
    const float* headw = (const float*)d_in[23];

    float *h, *xk, *xv, *xr, *k, *v, *r, *att, *kf;
    cudaGetSymbolAddress((void**)&h,   g_h);
    cudaGetSymbolAddress((void**)&xk,  g_xk);
    cudaGetSymbolAddress((void**)&xv,  g_xv);
    cudaGetSymbolAddress((void**)&xr,  g_xr);
    cudaGetSymbolAddress((void**)&k,   g_k);
    cudaGetSymbolAddress((void**)&v,   g_v);
    cudaGetSymbolAddress((void**)&r,   g_r);
    cudaGetSymbolAddress((void**)&att, g_att);
    cudaGetSymbolAddress((void**)&kf,  g_kf);

    dim3 blk(256);
    dim3 gH(H_ / GN,  BT_ / GM);   // (6, 32)   for N = 768
    dim3 gF(FF_ / GN, BT_ / GM);   // (24, 32)  for N = 3072

    // block 0 pre-LN: h = LN(x, pre_ln)
    ln_kernel<<<BT_, blk>>>(x, prew, preb, h);

    for (int i = 0; i < L_; i++) {
        size_t oH  = (size_t)i * H_;
        size_t oHH = (size_t)i * H_ * H_;
        size_t oHF = (size_t)i * H_ * FF_;

        // --- time mixing ---
        prep_mix<<<BT_, blk>>>(h, ln1w + oH, ln1b + oH,
                               amk + oH, amv + oH, amr + oH, xk, xv, xr);
        sgemm<0><<<gH, blk>>>(xk, Wk + oHH, k,  nullptr, BT_, H_, H_);
        sgemm<0><<<gH, blk>>>(xv, Wv + oHH, v,  nullptr, BT_, H_, H_);
        sgemm<1><<<gH, blk>>>(xr, Wr + oHH, r,  nullptr, BT_, H_, H_);
        wkv_kernel<<<(B_ * H_ + 255) / 256, blk>>>(k, v, r, td + oH, tf + oH, att);
        sgemm<2><<<gH, blk>>>(att, Wo + oHH, h, nullptr, BT_, H_, H_);

        // --- channel mixing ---
        prep_mix<<<BT_, blk>>>(h, ln2w + oH, ln2b + oH,
                               fmk + oH, nullptr, fmr + oH, xk, nullptr, xr);
        sgemm<4><<<gF, blk>>>(xk, Fk + oHF, kf, nullptr, BT_, FF_, H_);
        sgemm<1><<<gH, blk>>>(xr, Fr + oHH, r,  nullptr, BT_, H_, H_);
        sgemm<3><<<gH, blk>>>(kf, Fv + oHF, h,  r,       BT_, H_, FF_);
    }

    // final LN (in place; each block owns its row) + head projection
    ln_kernel<<<BT_, blk>>>(h, lnow, lnob, h);
    sgemm<0><<<gH, blk>>>(h, headw, (float*)d_out, nullptr, BT_, H_, H_);
}